// round 17
// baseline (speedup 1.0000x reference)
#include <cuda_runtime.h>
#include <cuda_fp16.h>
#include <cstdint>

// ROIAlign: features (4, 64, 38, 38) fp32, rois (4, 2904, 4) -> (11616, 64, 7, 7).
//
// R17 = R16 (fp16 NHWC, one LDG.128/corner, HFMA2 blend, mid-pad STS, TMA
// flush, RPB=3, 5 blocks/SM) + Programmatic Dependent Launch:
//   - kernel1 triggers launch_dependents after its stores
//   - kernel2 computes its first ROI's weights BEFORE griddepcontrol.wait
//     (depends only on rois), hiding the ~4.5us transpose prologue + launch
//     ramp behind kernel1.

#define FB 4
#define FH 38
#define FW 38
#define FC 64
#define OS 7
#define PLANE (FH * FW)               // 1444
#define PER_ROI (FC * OS * OS)        // 3136
#define NPIX (OS * OS)                // 49
#define HALF_BYTES (PER_ROI * 2)      // 6272 B per staging half
#define STAGE_F (PER_ROI + 4)         // 3140 floats (12560 B)
#define RPB 3                          // ROIs per block

__device__ __half g_nhwc[FB * PLANE * FC];   // [b][h][w][c] fp16, 0.74 MB

// ---------------- kernel 1: NCHW fp32 -> NHWC fp16 transpose ----------------
__global__ __launch_bounds__(256)
void nchw2nhwc_kernel(const float* __restrict__ feat)
{
    __shared__ float tile[32][33];
    const int b = blockIdx.z;
    const int hw0 = blockIdx.x * 32;
    const int c0 = blockIdx.y * 32;

    const float* in = feat + (size_t)b * FC * PLANE;
    __half* outp = g_nhwc + (size_t)b * PLANE * FC;

    const int tx = threadIdx.x;
    const int ty = threadIdx.y;

#pragma unroll
    for (int i = 0; i < 32; i += 8) {
        const int c = c0 + ty + i;
        const int hw = hw0 + tx;
        if (hw < PLANE)
            tile[ty + i][tx] = in[c * PLANE + hw];
    }
    __syncthreads();
#pragma unroll
    for (int i = 0; i < 32; i += 8) {
        const int hw = hw0 + ty + i;
        const int c = c0 + tx;
        if (hw < PLANE)
            outp[hw * FC + c] = __float2half(tile[tx][ty + i]);
    }

    // PDL: allow dependent grid to launch (stores above are visible to
    // dependents that execute griddepcontrol.wait)
    asm volatile("griddepcontrol.launch_dependents;" ::: "memory");
}

// 8 fp16 channels in one 16B load
struct alignas(16) half8 { __half2 h[4]; };

struct WSet {
    __half2 h00, h01, h10, h11;
    int o00, o01, o10, o11;
};

__device__ __forceinline__ WSet make_wset(float4 r, int ox, int oy)
{
    WSet ws;
    const float rw = fmaxf(r.z - r.x, 1.0f);
    const float rh = fmaxf(r.w - r.y, 1.0f);

    const float x = fmaf((float)ox * (1.0f / 6.0f), rw, r.x);
    const float y = fmaf((float)oy * (1.0f / 6.0f), rh, r.y);

    const float x0f = floorf(x);
    const float y0f = floorf(y);
    const float fx = x - x0f;
    const float fy = y - y0f;

    const int x0 = (int)x0f;             // in [0, 38]
    const int y0 = (int)y0f;

    const float wx1 = (x0 <= FW - 2) ? fx : 0.0f;
    const float wx0 = (x0 <= FW - 1) ? 1.0f - fx : 0.0f;
    const float wy1 = (y0 <= FH - 2) ? fy : 0.0f;
    const float wy0 = (y0 <= FH - 1) ? 1.0f - fy : 0.0f;

    const int xi0 = min(x0, FW - 1);
    const int xi1 = min(x0 + 1, FW - 1);
    const int yi0 = min(y0, FH - 1);
    const int yi1 = min(y0 + 1, FH - 1);

    ws.h00 = __float2half2_rn(wx0 * wy0);
    ws.h01 = __float2half2_rn(wx1 * wy0);
    ws.h10 = __float2half2_rn(wx0 * wy1);
    ws.h11 = __float2half2_rn(wx1 * wy1);

    ws.o00 = (yi0 * FW + xi0) * FC;
    ws.o01 = (yi0 * FW + xi1) * FC;
    ws.o10 = (yi1 * FW + xi0) * FC;
    ws.o11 = (yi1 * FW + xi1) * FC;
    return ws;
}

// ---------------- kernel 2: ROIAlign, 3 ROIs/block, HFMA2 + TMA ----------------
// blockDim = (8, 49) = 392 threads, 5 blocks/SM.
__global__ __launch_bounds__(392, 5)
void roialign_nhwc_kernel(const float* __restrict__ rois,
                          float* __restrict__ out,
                          int blocks_per_batch)
{
    __shared__ __align__(16) float s[RPB][STAGE_F];   // 37.7 KB

    const int cg = threadIdx.x;          // 0..7
    const int p = threadIdx.y;           // 0..48
    const int ox = p % OS;
    const int oy = p / OS;
    const int pad = (cg >= 4) ? 4 : 0;
    const int sbase = (8 * cg) * NPIX + p + pad;

    const int n0 = blockIdx.x * RPB;
    const int b = blockIdx.x / blocks_per_batch;   // constant per block

    // ---- pre-wait work: depends only on rois (input), not on g_nhwc ----
    WSet ws = make_wset(__ldg(reinterpret_cast<const float4*>(rois) + n0),
                        ox, oy);

    // PDL: wait for nchw2nhwc_kernel's table before touching g_nhwc
    asm volatile("griddepcontrol.wait;" ::: "memory");

    const __half* __restrict__ fb =
        g_nhwc + (size_t)b * PLANE * FC + 8 * cg;

#pragma unroll
    for (int i = 0; i < RPB; i++) {
        const int n = n0 + i;
        float* __restrict__ sb = s[i];

        if (i > 0)
            ws = make_wset(__ldg(reinterpret_cast<const float4*>(rois) + n),
                           ox, oy);

        // ---- gather: 4 x LDG.128 + HFMA2 blend ----
        const half8 v00 = *reinterpret_cast<const half8*>(fb + ws.o00);
        const half8 v01 = *reinterpret_cast<const half8*>(fb + ws.o01);
        const half8 v10 = *reinterpret_cast<const half8*>(fb + ws.o10);
        const half8 v11 = *reinterpret_cast<const half8*>(fb + ws.o11);

        __half2 acc[4];
#pragma unroll
        for (int k = 0; k < 4; k++) {
            acc[k] = __hmul2(ws.h11, v11.h[k]);
            acc[k] = __hfma2(ws.h10, v10.h[k], acc[k]);
            acc[k] = __hfma2(ws.h01, v01.h[k], acc[k]);
            acc[k] = __hfma2(ws.h00, v00.h[k], acc[k]);
        }

        // ---- stage: conflict-free STS via mid-pad (fp32 output) ----
#pragma unroll
        for (int k = 0; k < 4; k++) {
            const float2 f = __half22float2(acc[k]);
            sb[sbase + (2 * k + 0) * NPIX] = f.x;
            sb[sbase + (2 * k + 1) * NPIX] = f.y;
        }

        __syncthreads();                 // one barrier per ROI

        // ---- flush: thread 0 issues bulk smem->gmem (TMA), NO wait ----
        if (cg == 0 && p == 0) {
            asm volatile("fence.proxy.async.shared::cta;" ::: "memory");

            uint32_t s_addr;
            asm("{ .reg .u64 t; cvta.to.shared.u64 t, %1; cvt.u32.u64 %0, t; }"
                : "=r"(s_addr) : "l"(sb));
            const uint64_t g_addr =
                (uint64_t)(uintptr_t)(out + (size_t)n * PER_ROI);

            asm volatile(
                "cp.async.bulk.global.shared::cta.bulk_group [%0], [%1], %2;"
                :: "l"(g_addr), "r"(s_addr), "r"(HALF_BYTES) : "memory");
            asm volatile(
                "cp.async.bulk.global.shared::cta.bulk_group [%0], [%1], %2;"
                :: "l"(g_addr + HALF_BYTES), "r"(s_addr + HALF_BYTES + 16),
                   "r"(HALF_BYTES) : "memory");
            asm volatile("cp.async.bulk.commit_group;" ::: "memory");
        }
    }

    // drain all TMA stores before block exit
    if (cg == 0 && p == 0)
        asm volatile("cp.async.bulk.wait_group 0;" ::: "memory");
}

extern "C" void kernel_launch(void* const* d_in, const int* in_sizes, int n_in,
                              void* d_out, int out_size)
{
    const float* feat = (const float*)d_in[0];   // (B, 64, 38, 38)
    const float* rois = (const float*)d_in[1];   // (B, Nb, 4)
    float* out = (float*)d_out;

    const int B = in_sizes[0] / (FC * PLANE);    // 4
    const int n_roi = in_sizes[1] / 4;           // 11616
    const int nb = n_roi / B;                    // 2904

    dim3 tgrid((PLANE + 31) / 32, FC / 32, B);
    dim3 tblock(32, 8);
    nchw2nhwc_kernel<<<tgrid, tblock>>>(feat);

    // kernel2 with programmatic dependent launch on kernel1
    cudaLaunchConfig_t cfg = {};
    cfg.gridDim = dim3(n_roi / RPB, 1, 1);
    cfg.blockDim = dim3(8, 49, 1);
    cfg.dynamicSmemBytes = 0;
    cfg.stream = 0;
    cudaLaunchAttribute attrs[1];
    attrs[0].id = cudaLaunchAttributeProgrammaticStreamSerialization;
    attrs[0].val.programmaticStreamSerializationAllowed = 1;
    cfg.attrs = attrs;
    cfg.numAttrs = 1;
    cudaLaunchKernelEx(&cfg, roialign_nhwc_kernel, rois, out, nb / RPB);
}